// round 13
// baseline (speedup 1.0000x reference)
#include <cuda_runtime.h>
#include <math.h>

// mask [8,256,256] fp32 -> EDT (separable squared) -> normalize by global max -> sigmoid.
// 2-kernel pipeline:
//   k_row : warp-per-row; 2x LDG.128 + nibble-shfl bitmap; nearest-set-bit;
//           stores PRE-SQUARED float distances -> g_tmp (L2-resident).
//           Also resets barrier counter + global max (stream-ordered => graph-safe).
//   k_fuse: 256 blocks x 512 thr (8 cols/block, 4 outputs/thread). Joint-k pruned
//           column min-plus on PAD-64 smem (no bounds checks for k<=64), per-block
//           atomicMax, single 256-arrival spin barrier, fused sigmoid epilogue.
constexpr int B_ = 8;
constexpr int H_ = 256;
constexpr int W_ = 256;
constexpr int NT = B_ * H_ * W_;
constexpr float THR   = 0.5f;
constexpr float INF_F = 1e10f;
constexpr int BIG = 1 << 29;

constexpr int NBLK2 = 256;         // 8 images * 32 column-tiles
constexpr int NTHR2 = 512;
constexpr int CPB2  = 8;           // columns per k_fuse block
constexpr int OUTS  = 4;           // outputs per thread (rows y = yb + i*64)
constexpr int PAD   = 64;          // smem row padding (unchecked k range)
constexpr int SROWS = H_ + 2 * PAD;  // 384

__device__ float    g_tmp[NT];     // pass-1 squared distances (1e10 = empty row)
__device__ unsigned g_max;         // max d2 (float bits, nonneg)
__device__ unsigned g_cnt;         // barrier counter

// ---------------------------------------------------------------------------
// k_row: 256 blocks x 256 thr; warp handles one row.
__global__ __launch_bounds__(256) void k_row(const float* __restrict__ mask) {
    const int lane = threadIdx.x & 31;
    const int warp = threadIdx.x >> 5;
    const int row  = blockIdx.x * 8 + warp;        // b*H + y

    if (blockIdx.x == 0 && threadIdx.x == 0) { g_cnt = 0u; g_max = 0u; }

    // Load whole row: 2 x float4 per lane
    const float4* row4 = reinterpret_cast<const float4*>(mask + row * W_);
    const float4 a = row4[lane];
    const float4 bq = row4[lane + 32];

    // nibble -> 32-bit words via shfl-or; lanes 8g..8g+7 hold word g
    unsigned va = ((a.x > THR ? 1u : 0u) | (a.y > THR ? 2u : 0u)
                 | (a.z > THR ? 4u : 0u) | (a.w > THR ? 8u : 0u)) << ((lane & 7) * 4);
    unsigned vb = ((bq.x > THR ? 1u : 0u) | (bq.y > THR ? 2u : 0u)
                 | (bq.z > THR ? 4u : 0u) | (bq.w > THR ? 8u : 0u)) << ((lane & 7) * 4);
    va |= __shfl_xor_sync(0xffffffffu, va, 1);
    vb |= __shfl_xor_sync(0xffffffffu, vb, 1);
    va |= __shfl_xor_sync(0xffffffffu, va, 2);
    vb |= __shfl_xor_sync(0xffffffffu, vb, 2);
    va |= __shfl_xor_sync(0xffffffffu, va, 4);
    vb |= __shfl_xor_sync(0xffffffffu, vb, 4);

    unsigned w[8];
    #pragma unroll
    for (int j = 0; j < 4; ++j) {
        w[j]     = __shfl_sync(0xffffffffu, va, j * 8);
        w[4 + j] = __shfl_sync(0xffffffffu, vb, j * 8);
    }

    float* trow = g_tmp + row * W_;
    const unsigned mLo = 0xFFFFFFFFu >> (31 - lane);
    const unsigned mHi = 0xFFFFFFFFu << lane;

    #pragma unroll
    for (int j = 0; j < 8; ++j) {                  // pixel x = 32*j + lane
        int dl = BIG, dr = BIG;
        unsigned m = w[j] & mLo;
        if (m) dl = lane - (31 - __clz(m));
        #pragma unroll
        for (int wi = j - 1; wi >= 0; --wi)
            if (dl == BIG) {
                const unsigned ww = w[wi];
                if (ww) dl = (j - wi) * 32 + lane - (31 - __clz(ww));
            }
        m = w[j] & mHi;
        if (m) dr = (__ffs(m) - 1) - lane;
        #pragma unroll
        for (int wi = j + 1; wi < 8; ++wi)
            if (dr == BIG) {
                const unsigned ww = w[wi];
                if (ww) dr = (wi - j) * 32 + (__ffs(ww) - 1) - lane;
            }
        const int d = min(dl, dr);
        trow[j * 32 + lane] = (d <= 255) ? (float)(d * d) : INF_F;  // pre-squared
    }
}

// ---------------------------------------------------------------------------
// k_fuse: 256 blocks x 512 thr. Block = (image b, 8-column tile x0).
__global__ __launch_bounds__(NTHR2) void k_fuse(float* __restrict__ out) {
    const int blk = blockIdx.x;
    const int b   = blk >> 5;                      // image
    const int x0  = (blk & 31) * CPB2;             // column tile base
    const int t   = threadIdx.x;

    __shared__ float tmp2[SROWS * CPB2];           // padded squared values, 12KB
    __shared__ float red[16];
    __shared__ float s_scale;

    // Fill padded smem: rows [0,PAD) and [PAD+H,SROWS) = INF, middle from g_tmp.
    {
        const float* src = g_tmp + b * H_ * W_ + x0;
        #pragma unroll
        for (int idx = t; idx < SROWS * CPB2; idx += NTHR2) {
            const int r = idx >> 3;                // padded row
            const int cc = idx & 7;
            const int y = r - PAD;
            tmp2[idx] = (unsigned(y) < unsigned(H_)) ? src[y * W_ + cc] : INF_F;
        }
    }
    __syncthreads();

    const int c  = t & 7;                          // column within tile
    const int yb = t >> 3;                         // 0..63
    float best[OUTS];
    float bmax = 0.0f;
    #pragma unroll
    for (int i = 0; i < OUTS; ++i) {
        best[i] = tmp2[(PAD + yb + i * 64) * CPB2 + c];
        bmax = fmaxf(bmax, best[i]);
    }

    // Unchecked pruned loop (padded: valid for k <= PAD)
    int k = 1;
    #pragma unroll 1
    for (; k <= PAD; ++k) {
        const float kk = (float)(k * k);
        if (kk >= bmax) break;                     // exact prune (tmp2 >= 0)
        bmax = 0.0f;
        #pragma unroll
        for (int i = 0; i < OUTS; ++i) {
            const int yi = PAD + yb + i * 64;
            best[i] = fminf(best[i], kk + tmp2[(yi - k) * CPB2 + c]);
            best[i] = fminf(best[i], kk + tmp2[(yi + k) * CPB2 + c]);
            bmax = fmaxf(bmax, best[i]);
        }
    }
    // Rare fallback (near-empty images): checked continuation k in (PAD, H)
    if (k > PAD) {
        #pragma unroll 1
        for (; k < H_; ++k) {
            const float kk = (float)(k * k);
            if (kk >= bmax) break;
            bmax = 0.0f;
            #pragma unroll
            for (int i = 0; i < OUTS; ++i) {
                const int y = yb + i * 64;
                const int ym = y - k;
                if (ym >= 0)  best[i] = fminf(best[i], kk + tmp2[(PAD + ym) * CPB2 + c]);
                const int yp = y + k;
                if (yp < H_)  best[i] = fminf(best[i], kk + tmp2[(PAD + yp) * CPB2 + c]);
                bmax = fmaxf(bmax, best[i]);
            }
        }
    }

    // block max -> global atomic -> 256-arrival grid barrier (busy poll)
    float lmax = bmax;
    #pragma unroll
    for (int off = 16; off; off >>= 1)
        lmax = fmaxf(lmax, __shfl_xor_sync(0xffffffffu, lmax, off));
    if ((t & 31) == 0) red[t >> 5] = lmax;
    __syncthreads();
    if (t == 0) {
        float bm = red[0];
        #pragma unroll
        for (int i = 1; i < 16; ++i) bm = fmaxf(bm, red[i]);
        atomicMax(&g_max, __float_as_uint(bm));
        __threadfence();
        atomicAdd(&g_cnt, 1u);
        while (__ldcg(&g_cnt) < (unsigned)NBLK2) { }
        __threadfence();
        s_scale = 50.0f / (sqrtf(__uint_as_float(__ldcg(&g_max))) + 1.0f);
    }
    __syncthreads();
    const float s = s_scale;

    // fused epilogue straight from registers
    float* obase = out + b * H_ * W_ + x0 + c;
    #pragma unroll
    for (int i = 0; i < OUTS; ++i) {
        const int y = yb + i * 64;
        obase[y * W_] = __fdividef(2.0f, 1.0f + __expf(sqrtf(best[i]) * s));
    }
}

// ---------------------------------------------------------------------------
extern "C" void kernel_launch(void* const* d_in, const int* in_sizes, int n_in,
                              void* d_out, int out_size) {
    const float* mask = (const float*)d_in[0];
    float* out = (float*)d_out;
    k_row<<<B_ * H_ / 8, 256>>>(mask);
    k_fuse<<<NBLK2, NTHR2>>>(out);
}